// round 9
// baseline (speedup 1.0000x reference)
#include <cuda_runtime.h>
#include <cuda_bf16.h>
#include <cstdint>

// DySample: x(8,256,64,64), W_off(32,256), b_off(32) -> out(8,256,128,128), fp32.
//   A (R6 config): offsets = W_off @ x + b_off -> final sample coords -> 4MB scratch.
//   B: bilinear gather with dual-parity padded smem rows: corner pair is always an
//      aligned float2 in one of two shifted copies -> 2 LDS.64 + 4 FMA + 1 STG per k.
// ix = w + (0.25*off_x + ipx), iy = h + (0.25*off_y + ipy);
// j = g*4 + ry*2 + rx; o_x = j, o_y = 16 + j; ipx = (j&1)?+.25:-.25, ipy = ((j>>1)&1)?+.25:-.25

#define Bn 8
#define Cn 256
#define Hn 64
#define Wn 64
#define Gn 4
#define NPOS 4096
#define OH 128
#define OW 128

typedef unsigned long long ull;

__device__ float d_coord[Bn * 32 * NPOS];   // 4 MB scratch

__device__ __forceinline__ void ffma2(ull &d, ull a, ull b) {
    asm("fma.rn.f32x2 %0, %1, %2, %0;" : "+l"(d) : "l"(a), "l"(b));
}
__device__ __forceinline__ ull pack2(float lo, float hi) {
    ull r;
    asm("mov.b64 %0, {%1, %2};" : "=l"(r) : "f"(lo), "f"(hi));
    return r;
}
__device__ __forceinline__ void unpack2(ull v, float &lo, float &hi) {
    asm("mov.b64 {%0, %1}, %2;" : "=f"(lo), "=f"(hi) : "l"(v));
}

// ---------------- Kernel A: offset GEMM (R6 config) ----------------
// grid (128, 8), 256 threads. Block = 32 positions; thread = (pos, cq), cq owns 32 ch.
__global__ __launch_bounds__(256) void offset_kernel(
    const float* __restrict__ x,
    const float* __restrict__ Woff,
    const float* __restrict__ boff)
{
    __shared__ __align__(16) char sraw[32768];
    ull (*Wp)[256] = reinterpret_cast<ull(*)[256]>(sraw);            // [16][256] 32KB
    float2 (*red)[8][32] = reinterpret_cast<float2(*)[8][32]>(sraw); // [16][8][32] 32KB

    const int tid  = threadIdx.x;
    const int b    = blockIdx.y;
    const int posl = tid & 31;
    const int cq   = tid >> 5;                 // 0..7 (warp-uniform)
    const int gpos = blockIdx.x * 32 + posl;

    #pragma unroll
    for (int i = 0; i < 16; i++) {
        const int idx = i * 256 + tid;
        const int p = idx >> 8, c = idx & 255;
        Wp[p][c] = pack2(Woff[p * Cn + c], Woff[(p + 16) * Cn + c]);
    }
    __syncthreads();

    ull acc[16];
    #pragma unroll
    for (int p = 0; p < 16; p++) acc[p] = 0ull;

    const float* xb = x + (size_t)b * Cn * NPOS + gpos;
    const int c0 = cq * 32;

    #pragma unroll 4
    for (int cc = 0; cc < 32; cc += 2) {
        const int c = c0 + cc;
        const float xv0 = __ldg(xb + (size_t)c * NPOS);
        const float xv1 = __ldg(xb + (size_t)(c + 1) * NPOS);
        const ull xp0 = pack2(xv0, xv0);
        const ull xp1 = pack2(xv1, xv1);
        #pragma unroll
        for (int p = 0; p < 16; p++) {
            ulonglong2 wv = *(const ulonglong2*)&Wp[p][c];
            ffma2(acc[p], wv.x, xp0);
            ffma2(acc[p], wv.y, xp1);
        }
    }
    __syncthreads();                      // Wp dead; reuse smem

    #pragma unroll
    for (int p = 0; p < 16; p++) {
        float lo, hi;
        unpack2(acc[p], lo, hi);
        red[p][cq][posl] = make_float2(lo, hi);
    }
    __syncthreads();

    const int pp = tid >> 5;
    const int w = gpos & 63;
    const int h = gpos >> 6;
    #pragma unroll
    for (int t = 0; t < 2; t++) {
        const int p = pp * 2 + t;
        float2 s = red[p][0][posl];
        #pragma unroll
        for (int q = 1; q < 8; q++) {
            float2 u = red[p][q][posl];
            s.x += u.x; s.y += u.y;
        }
        const float ipx = (p & 1) ? 0.25f : -0.25f;
        const float ipy = ((p >> 1) & 1) ? 0.25f : -0.25f;
        const float cx = (float)w + 0.25f * (s.x + __ldg(boff + p)) + ipx;
        const float cy = (float)h + 0.25f * (s.y + __ldg(boff + p + 16)) + ipy;
        d_coord[(size_t)(b * 32 + p) * NPOS + gpos]      = cx;
        d_coord[(size_t)(b * 32 + p + 16) * NPOS + gpos] = cy;
    }
}

// ---------------- Kernel B: dual-parity smem bilinear gather -----------------
// grid (64, 8, 16) = (h, b, g*4+chunk). 256 threads. Stage 3 rows x 16 ch.
// Padded row P[0..66]: P[0]=d0, P[1..64]=d0..d63, P[65]=P[66]=d63.
// E[i] = P[i] (reads at even i), O[i] = P[i+1] (reads at even i).
__global__ __launch_bounds__(256) void gather_kernel(
    const float* __restrict__ x,
    float* __restrict__ out)
{
    __shared__ __align__(16) float Esm[3][16][68];   // 12.75 KB
    __shared__ __align__(16) float Osm[3][16][68];   // 12.75 KB
    __shared__ float sxy[2][4][64];                  // 2 KB

    const int tid   = threadIdx.x;
    const int h     = blockIdx.x;
    const int b     = blockIdx.y;
    const int g     = blockIdx.z >> 2;
    const int chunk = blockIdx.z & 3;
    const int cstage = b * Cn + g * 64 + chunk * 16;

    // stage coords for this group's 4 j's
    #pragma unroll
    for (int i = 0; i < 2; i++) {
        const int lin = i * 256 + tid;        // 0..511
        const int w  = lin & 63;
        const int jj = (lin >> 6) & 3;
        const int xy = lin >> 8;
        sxy[xy][jj][w] =
            d_coord[(size_t)(b * 32 + g * 4 + jj + xy * 16) * NPOS + (h << 6) + w];
    }

    // stage rows: warp per row-task; lane = w (conflict-free STS, coalesced LDG)
    const int warp = tid >> 5, lane = tid & 31;
    #pragma unroll
    for (int it = 0; it < 6; it++) {
        const int t  = warp * 6 + it;         // 0..47
        const int rr = t % 3;
        const int c  = t / 3;
        const int rowy = min(max(h - 1 + rr, 0), Hn - 1);
        const float* rowp = x + (((size_t)(cstage + c)) * Hn + rowy) * Wn;
        const float d0 = __ldg(rowp + lane);
        const float d1 = __ldg(rowp + lane + 32);
        Osm[rr][c][lane]      = d0;           // O[w] = P[w+1] = d[w]
        Osm[rr][c][lane + 32] = d1;
        Esm[rr][c][lane + 1]  = d0;           // E[w+1] = P[w+1] = d[w]
        Esm[rr][c][lane + 33] = d1;
        if (lane == 0)  Esm[rr][c][0] = d0;   // P[0] = d0
        if (lane == 31) {                     // P[65] = P[66] = d63
            Esm[rr][c][65] = d1; Esm[rr][c][66] = d1;
            Osm[rr][c][64] = d1; Osm[rr][c][65] = d1;
        }
    }
    __syncthreads();

    const int ox  = tid & 127;
    const int sub = tid >> 7;                 // 0..1 -> 8 channels each
    const int wq = ox >> 1;
    const int rx = ox & 1;
    const int cloc  = sub * 8;
    const int cglob = cstage + cloc;

    #pragma unroll
    for (int ry = 0; ry < 2; ry++) {
        const int jj = ry * 2 + rx;
        const float ix = sxy[0][jj][wq];
        const float iy = sxy[1][jj][wq];
        const float xf = floorf(ix);
        const float yf = floorf(iy);
        const float wx = ix - xf;
        const float wy = iy - yf;
        const int xi = (int)xf;
        const int yi = (int)yf;
        const int y0 = min(max(yi, 0), Hn - 1);
        const int y1 = min(max(yi + 1, 0), Hn - 1);
        const int r0 = y0 - h + 1;
        const int r1 = y1 - h + 1;
        const int pE = min(max(xi + 1, 0), 65);   // corner pair = (P[pE], P[pE+1])
        const bool fast = ((unsigned)r0 <= 2u) && ((unsigned)r1 <= 2u);

        const float w1x = wx, w0x = 1.f - wx;
        const float w00 = (1.f - wy) * w0x, w01 = (1.f - wy) * w1x;
        const float w10 = wy * w0x,         w11 = wy * w1x;

        const int oy = 2 * h + ry;
        float* op = out + (((size_t)cglob * OH + oy) * OW + ox);

        if (__builtin_expect(fast, 1)) {
            const float* b0;
            const float* b1;
            if (pE & 1) {
                b0 = &Osm[r0][cloc][pE - 1];
                b1 = &Osm[r1][cloc][pE - 1];
            } else {
                b0 = &Esm[r0][cloc][pE];
                b1 = &Esm[r1][cloc][pE];
            }
            #pragma unroll
            for (int k = 0; k < 8; k++) {
                const float2 t = *(const float2*)(b0 + k * 68);
                const float2 u = *(const float2*)(b1 + k * 68);
                op[(size_t)k * (OH * OW)] =
                    w00 * t.x + w01 * t.y + w10 * u.x + w11 * u.y;
            }
        } else {
            const int x0 = min(max(xi, 0), Wn - 1);
            const int x1 = min(max(xi + 1, 0), Wn - 1);
            const int o00 = y0 * Wn + x0;
            const int o01 = y0 * Wn + x1;
            const int o10 = y1 * Wn + x0;
            const int o11 = y1 * Wn + x1;
            #pragma unroll
            for (int k = 0; k < 8; k++) {
                const float* p = x + (size_t)(cglob + k) * NPOS;
                const float v = w00 * __ldg(p + o00) + w01 * __ldg(p + o01)
                              + w10 * __ldg(p + o10) + w11 * __ldg(p + o11);
                op[(size_t)k * (OH * OW)] = v;
            }
        }
    }
}

extern "C" void kernel_launch(void* const* d_in, const int* in_sizes, int n_in,
                              void* d_out, int out_size) {
    const float* x    = (const float*)d_in[0];
    const float* Woff = (const float*)d_in[1];
    const float* boff = (const float*)d_in[2];
    float* out = (float*)d_out;

    dim3 gridA(128, Bn);
    offset_kernel<<<gridA, 256>>>(x, Woff, boff);

    dim3 gridB(Hn, Bn, 16);
    gather_kernel<<<gridB, 256>>>(x, out);
}

// round 10
// speedup vs baseline: 1.2869x; 1.2869x over previous
#include <cuda_runtime.h>
#include <cuda_bf16.h>
#include <cstdint>

// DySample: x(8,256,64,64), W_off(32,256), b_off(32) -> out(8,256,128,128), fp32.
//   A (R6 config, proven): offsets -> final sample coords -> 4MB scratch.
//   B: 3x3-neighborhood gather: lane = wq (stride-1 smem reads, conflict-free),
//      per-lane precomputed 3x3 weights for the 4 (rx,ry) outputs, float2 stores.
// ix = w + (0.25*off_x + ipx), iy = h + (0.25*off_y + ipy);
// j = g*4 + ry*2 + rx; o_x = j, o_y = 16 + j; ipx = (j&1)?+.25:-.25, ipy = ((j>>1)&1)?+.25:-.25

#define Bn 8
#define Cn 256
#define Hn 64
#define Wn 64
#define Gn 4
#define NPOS 4096
#define OH 128
#define OW 128

typedef unsigned long long ull;

__device__ float d_coord[Bn * 32 * NPOS];   // 4 MB scratch

__device__ __forceinline__ void ffma2(ull &d, ull a, ull b) {
    asm("fma.rn.f32x2 %0, %1, %2, %0;" : "+l"(d) : "l"(a), "l"(b));
}
__device__ __forceinline__ ull pack2(float lo, float hi) {
    ull r;
    asm("mov.b64 %0, {%1, %2};" : "=l"(r) : "f"(lo), "f"(hi));
    return r;
}
__device__ __forceinline__ void unpack2(ull v, float &lo, float &hi) {
    asm("mov.b64 {%0, %1}, %2;" : "=f"(lo), "=f"(hi) : "l"(v));
}

// ---------------- Kernel A: offset GEMM (R6 config, unchanged) ----------------
__global__ __launch_bounds__(256) void offset_kernel(
    const float* __restrict__ x,
    const float* __restrict__ Woff,
    const float* __restrict__ boff)
{
    __shared__ __align__(16) char sraw[32768];
    ull (*Wp)[256] = reinterpret_cast<ull(*)[256]>(sraw);            // [16][256] 32KB
    float2 (*red)[8][32] = reinterpret_cast<float2(*)[8][32]>(sraw); // [16][8][32] 32KB

    const int tid  = threadIdx.x;
    const int b    = blockIdx.y;
    const int posl = tid & 31;
    const int cq   = tid >> 5;                 // 0..7 (warp-uniform)
    const int gpos = blockIdx.x * 32 + posl;

    #pragma unroll
    for (int i = 0; i < 16; i++) {
        const int idx = i * 256 + tid;
        const int p = idx >> 8, c = idx & 255;
        Wp[p][c] = pack2(Woff[p * Cn + c], Woff[(p + 16) * Cn + c]);
    }
    __syncthreads();

    ull acc[16];
    #pragma unroll
    for (int p = 0; p < 16; p++) acc[p] = 0ull;

    const float* xb = x + (size_t)b * Cn * NPOS + gpos;
    const int c0 = cq * 32;

    #pragma unroll 4
    for (int cc = 0; cc < 32; cc += 2) {
        const int c = c0 + cc;
        const float xv0 = __ldg(xb + (size_t)c * NPOS);
        const float xv1 = __ldg(xb + (size_t)(c + 1) * NPOS);
        const ull xp0 = pack2(xv0, xv0);
        const ull xp1 = pack2(xv1, xv1);
        #pragma unroll
        for (int p = 0; p < 16; p++) {
            ulonglong2 wv = *(const ulonglong2*)&Wp[p][c];
            ffma2(acc[p], wv.x, xp0);
            ffma2(acc[p], wv.y, xp1);
        }
    }
    __syncthreads();

    #pragma unroll
    for (int p = 0; p < 16; p++) {
        float lo, hi;
        unpack2(acc[p], lo, hi);
        red[p][cq][posl] = make_float2(lo, hi);
    }
    __syncthreads();

    const int pp = tid >> 5;
    const int w = gpos & 63;
    const int h = gpos >> 6;
    #pragma unroll
    for (int t = 0; t < 2; t++) {
        const int p = pp * 2 + t;
        float2 s = red[p][0][posl];
        #pragma unroll
        for (int q = 1; q < 8; q++) {
            float2 u = red[p][q][posl];
            s.x += u.x; s.y += u.y;
        }
        const float ipx = (p & 1) ? 0.25f : -0.25f;
        const float ipy = ((p >> 1) & 1) ? 0.25f : -0.25f;
        const float cx = (float)w + 0.25f * (s.x + __ldg(boff + p)) + ipx;
        const float cy = (float)h + 0.25f * (s.y + __ldg(boff + p + 16)) + ipy;
        d_coord[(size_t)(b * 32 + p) * NPOS + gpos]      = cx;
        d_coord[(size_t)(b * 32 + p + 16) * NPOS + gpos] = cy;
    }
}

// ---------------- Kernel B: 3x3-neighborhood gather --------------------------
// grid (64, 8, 8) = (h, b, g*2+half32). 256 threads. Stage 3 rows x 32 ch.
// Warp w: half = w&1 -> wq = 32*half + lane; channels (w>>1)*8 .. +7.
__global__ __launch_bounds__(256) void gather_kernel(
    const float* __restrict__ x,
    float* __restrict__ out)
{
    __shared__ float xs[3][32][64];     // 24 KB, [row][c][w] (bank-aligned rows)
    __shared__ float sxy[2][4][64];     // 2 KB

    const int tid  = threadIdx.x;
    const int h    = blockIdx.x;
    const int b    = blockIdx.y;
    const int g    = blockIdx.z >> 1;
    const int half = blockIdx.z & 1;
    const int cstage = b * Cn + g * 64 + half * 32;

    // stage coords for this group's 4 j's
    #pragma unroll
    for (int i = 0; i < 2; i++) {
        const int lin = i * 256 + tid;        // 0..511
        const int w  = lin & 63;
        const int jj = (lin >> 6) & 3;
        const int xy = lin >> 8;
        sxy[xy][jj][w] =
            d_coord[(size_t)(b * 32 + g * 4 + jj + xy * 16) * NPOS + (h << 6) + w];
    }

    // stage 3 input rows (clamped) x 32 channels, float4 coalesced (R6 scheme)
    #pragma unroll
    for (int i = 0; i < 6; i++) {
        const int lin = i * 256 + tid;        // 0..1535
        const int w4 = lin & 15;
        const int rr = (lin >> 4) % 3;
        const int c  = lin / 48;              // 0..31
        const int rowy = min(max(h - 1 + rr, 0), Hn - 1);
        const float4 v = __ldg((const float4*)(x
            + (((size_t)(cstage + c)) * Hn + rowy) * Wn) + w4);
        *(float4*)&xs[rr][c][w4 * 4] = v;
    }
    __syncthreads();

    const int warp = tid >> 5, lane = tid & 31;
    const int wh = warp & 1;                  // which 32-wide wq half
    const int wq = wh * 32 + lane;
    const int kbase = (warp >> 1) * 8;        // 8 channels per warp

    // ---- per-lane 3x3 weights for j = 0..3 (exact, border-safe) ----
    // columns: {wq-1, wq, wq+1} (loads clamped; coefficients make clamp exact)
    // rows:    {h-1, h, h+1}
    float W9[4][9];
    #pragma unroll
    for (int j = 0; j < 4; j++) {
        const float ix = sxy[0][j][wq];
        const float iy = sxy[1][j][wq];
        const float xf = floorf(ix);
        const float yf = floorf(iy);
        const float wx = ix - xf;
        const float wy = iy - yf;
        const bool xh = (xf >= (float)wq);    // xi == wq (else wq-1)
        const bool yh = (yf >= (float)h);     // yi == h  (else h-1)
        const float xc0 = xh ? 0.f : 1.f - wx;
        const float xc1 = xh ? 1.f - wx : wx;
        const float xc2 = xh ? wx : 0.f;
        const float yc0 = yh ? 0.f : 1.f - wy;
        const float yc1 = yh ? 1.f - wy : wy;
        const float yc2 = yh ? wy : 0.f;
        W9[j][0] = yc0 * xc0; W9[j][1] = yc0 * xc1; W9[j][2] = yc0 * xc2;
        W9[j][3] = yc1 * xc0; W9[j][4] = yc1 * xc1; W9[j][5] = yc1 * xc2;
        W9[j][6] = yc2 * xc0; W9[j][7] = yc2 * xc1; W9[j][8] = yc2 * xc2;
    }
    const int xl = max(wq - 1, 0);
    const int xm = wq;
    const int xr = min(wq + 1, Wn - 1);

    const int oy0 = 2 * h;
    const int ox0 = 2 * wq;

    // ---- channel loop: 9 conflict-free LDS + 36 FFMA + 2 STG.64 ----
    #pragma unroll
    for (int kk = 0; kk < 8; kk++) {
        const int k = kbase + kk;
        float v0 = xs[0][k][xl], v1 = xs[0][k][xm], v2 = xs[0][k][xr];
        float v3 = xs[1][k][xl], v4 = xs[1][k][xm], v5 = xs[1][k][xr];
        float v6 = xs[2][k][xl], v7 = xs[2][k][xm], v8 = xs[2][k][xr];

        float a0 = W9[0][0]*v0 + W9[0][1]*v1 + W9[0][2]*v2
                 + W9[0][3]*v3 + W9[0][4]*v4 + W9[0][5]*v5
                 + W9[0][6]*v6 + W9[0][7]*v7 + W9[0][8]*v8;   // (rx=0, ry=0)
        float a1 = W9[1][0]*v0 + W9[1][1]*v1 + W9[1][2]*v2
                 + W9[1][3]*v3 + W9[1][4]*v4 + W9[1][5]*v5
                 + W9[1][6]*v6 + W9[1][7]*v7 + W9[1][8]*v8;   // (rx=1, ry=0)
        float a2 = W9[2][0]*v0 + W9[2][1]*v1 + W9[2][2]*v2
                 + W9[2][3]*v3 + W9[2][4]*v4 + W9[2][5]*v5
                 + W9[2][6]*v6 + W9[2][7]*v7 + W9[2][8]*v8;   // (rx=0, ry=1)
        float a3 = W9[3][0]*v0 + W9[3][1]*v1 + W9[3][2]*v2
                 + W9[3][3]*v3 + W9[3][4]*v4 + W9[3][5]*v5
                 + W9[3][6]*v6 + W9[3][7]*v7 + W9[3][8]*v8;   // (rx=1, ry=1)

        float* op = out + (((size_t)(cstage + k) * OH + oy0) * OW + ox0);
        *(float2*)op        = make_float2(a0, a1);
        *(float2*)(op + OW) = make_float2(a2, a3);
    }
}

extern "C" void kernel_launch(void* const* d_in, const int* in_sizes, int n_in,
                              void* d_out, int out_size) {
    const float* x    = (const float*)d_in[0];
    const float* Woff = (const float*)d_in[1];
    const float* boff = (const float*)d_in[2];
    float* out = (float*)d_out;

    dim3 gridA(128, Bn);
    offset_kernel<<<gridA, 256>>>(x, Woff, boff);

    dim3 gridB(Hn, Bn, 8);
    gather_kernel<<<gridB, 256>>>(x, out);
}

// round 11
// speedup vs baseline: 1.4516x; 1.1280x over previous
#include <cuda_runtime.h>
#include <cuda_bf16.h>
#include <cstdint>

// DySample: x(8,256,64,64), W_off(32,256), b_off(32) -> out(8,256,128,128), fp32.
//   A (R6 config, proven): offsets -> final sample coords -> 4MB scratch.
//   B: 3x3-neighborhood gather, lane = wq (conflict-free stride-1 LDS), with
//      separable per-j coefficients PACKED as f32x2 over the (rx0,rx1) pair:
//      24 ffma2 per channel, b64 stores are the packed result directly.
// ix = w + (0.25*off_x + ipx), iy = h + (0.25*off_y + ipy);
// j = g*4 + ry*2 + rx; o_x = j, o_y = 16 + j; ipx = (j&1)?+.25:-.25, ipy = ((j>>1)&1)?+.25:-.25

#define Bn 8
#define Cn 256
#define Hn 64
#define Wn 64
#define Gn 4
#define NPOS 4096
#define OH 128
#define OW 128

typedef unsigned long long ull;

__device__ float d_coord[Bn * 32 * NPOS];   // 4 MB scratch

__device__ __forceinline__ void ffma2(ull &d, ull a, ull b) {
    asm("fma.rn.f32x2 %0, %1, %2, %0;" : "+l"(d) : "l"(a), "l"(b));
}
__device__ __forceinline__ ull mul2(ull a, ull b) {
    ull r;
    asm("mul.rn.f32x2 %0, %1, %2;" : "=l"(r) : "l"(a), "l"(b));
    return r;
}
__device__ __forceinline__ ull pack2(float lo, float hi) {
    ull r;
    asm("mov.b64 %0, {%1, %2};" : "=l"(r) : "f"(lo), "f"(hi));
    return r;
}
__device__ __forceinline__ void unpack2(ull v, float &lo, float &hi) {
    asm("mov.b64 {%0, %1}, %2;" : "=f"(lo), "=f"(hi) : "l"(v));
}

// ---------------- Kernel A: offset GEMM (R6 config, unchanged) ----------------
__global__ __launch_bounds__(256) void offset_kernel(
    const float* __restrict__ x,
    const float* __restrict__ Woff,
    const float* __restrict__ boff)
{
    __shared__ __align__(16) char sraw[32768];
    ull (*Wp)[256] = reinterpret_cast<ull(*)[256]>(sraw);            // [16][256] 32KB
    float2 (*red)[8][32] = reinterpret_cast<float2(*)[8][32]>(sraw); // [16][8][32] 32KB

    const int tid  = threadIdx.x;
    const int b    = blockIdx.y;
    const int posl = tid & 31;
    const int cq   = tid >> 5;                 // 0..7 (warp-uniform)
    const int gpos = blockIdx.x * 32 + posl;

    #pragma unroll
    for (int i = 0; i < 16; i++) {
        const int idx = i * 256 + tid;
        const int p = idx >> 8, c = idx & 255;
        Wp[p][c] = pack2(Woff[p * Cn + c], Woff[(p + 16) * Cn + c]);
    }
    __syncthreads();

    ull acc[16];
    #pragma unroll
    for (int p = 0; p < 16; p++) acc[p] = 0ull;

    const float* xb = x + (size_t)b * Cn * NPOS + gpos;
    const int c0 = cq * 32;

    #pragma unroll 4
    for (int cc = 0; cc < 32; cc += 2) {
        const int c = c0 + cc;
        const float xv0 = __ldg(xb + (size_t)c * NPOS);
        const float xv1 = __ldg(xb + (size_t)(c + 1) * NPOS);
        const ull xp0 = pack2(xv0, xv0);
        const ull xp1 = pack2(xv1, xv1);
        #pragma unroll
        for (int p = 0; p < 16; p++) {
            ulonglong2 wv = *(const ulonglong2*)&Wp[p][c];
            ffma2(acc[p], wv.x, xp0);
            ffma2(acc[p], wv.y, xp1);
        }
    }
    __syncthreads();

    #pragma unroll
    for (int p = 0; p < 16; p++) {
        float lo, hi;
        unpack2(acc[p], lo, hi);
        red[p][cq][posl] = make_float2(lo, hi);
    }
    __syncthreads();

    const int pp = tid >> 5;
    const int w = gpos & 63;
    const int h = gpos >> 6;
    #pragma unroll
    for (int t = 0; t < 2; t++) {
        const int p = pp * 2 + t;
        float2 s = red[p][0][posl];
        #pragma unroll
        for (int q = 1; q < 8; q++) {
            float2 u = red[p][q][posl];
            s.x += u.x; s.y += u.y;
        }
        const float ipx = (p & 1) ? 0.25f : -0.25f;
        const float ipy = ((p >> 1) & 1) ? 0.25f : -0.25f;
        const float cx = (float)w + 0.25f * (s.x + __ldg(boff + p)) + ipx;
        const float cy = (float)h + 0.25f * (s.y + __ldg(boff + p + 16)) + ipy;
        d_coord[(size_t)(b * 32 + p) * NPOS + gpos]      = cx;
        d_coord[(size_t)(b * 32 + p + 16) * NPOS + gpos] = cy;
    }
}

// ---------------- Kernel B: 3x3 gather, packed-separable weights -------------
// grid (64, 8, 8) = (h, b, g*2+half32). 256 threads. Stage 3 rows x 32 ch.
// Warp w: half = w&1 -> wq = 32*half + lane; channels (w>>1)*8 .. +7.
__global__ __launch_bounds__(256, 4) void gather_kernel(
    const float* __restrict__ x,
    float* __restrict__ out)
{
    __shared__ float xs[3][32][64];     // 24 KB, [row][c][w] (bank-aligned rows)
    __shared__ float sxy[2][4][64];     // 2 KB

    const int tid  = threadIdx.x;
    const int h    = blockIdx.x;
    const int b    = blockIdx.y;
    const int g    = blockIdx.z >> 1;
    const int half = blockIdx.z & 1;
    const int cstage = b * Cn + g * 64 + half * 32;

    // stage coords for this group's 4 j's
    #pragma unroll
    for (int i = 0; i < 2; i++) {
        const int lin = i * 256 + tid;        // 0..511
        const int w  = lin & 63;
        const int jj = (lin >> 6) & 3;
        const int xy = lin >> 8;
        sxy[xy][jj][w] =
            d_coord[(size_t)(b * 32 + g * 4 + jj + xy * 16) * NPOS + (h << 6) + w];
    }

    // stage 3 input rows (clamped) x 32 channels, float4 coalesced
    #pragma unroll
    for (int i = 0; i < 6; i++) {
        const int lin = i * 256 + tid;        // 0..1535
        const int w4 = lin & 15;
        const int rr = (lin >> 4) % 3;
        const int c  = lin / 48;              // 0..31
        const int rowy = min(max(h - 1 + rr, 0), Hn - 1);
        const float4 v = __ldg((const float4*)(x
            + (((size_t)(cstage + c)) * Hn + rowy) * Wn) + w4);
        *(float4*)&xs[rr][c][w4 * 4] = v;
    }
    __syncthreads();

    const int warp = tid >> 5, lane = tid & 31;
    const int wh = warp & 1;
    const int wq = wh * 32 + lane;
    const int kbase = (warp >> 1) * 8;        // 8 channels per warp

    // ---- packed separable coefficients: (rx=0, rx=1) pairs per ry ----
    // columns {wq-1, wq, wq+1}, rows {h-1, h, h+1}; clamp exact by construction.
    ull xcp[2][3], ycp[2][3];
    #pragma unroll
    for (int ry = 0; ry < 2; ry++) {
        float xc[2][3], yc[2][3];
        #pragma unroll
        for (int rx = 0; rx < 2; rx++) {
            const int j = ry * 2 + rx;
            const float ix = sxy[0][j][wq];
            const float iy = sxy[1][j][wq];
            const float xf = floorf(ix);
            const float yf = floorf(iy);
            const float wx = ix - xf;
            const float wy = iy - yf;
            const bool xh = (xf >= (float)wq);
            const bool yh = (yf >= (float)h);
            xc[rx][0] = xh ? 0.f : 1.f - wx;
            xc[rx][1] = xh ? 1.f - wx : wx;
            xc[rx][2] = xh ? wx : 0.f;
            yc[rx][0] = yh ? 0.f : 1.f - wy;
            yc[rx][1] = yh ? 1.f - wy : wy;
            yc[rx][2] = yh ? wy : 0.f;
        }
        #pragma unroll
        for (int i = 0; i < 3; i++) {
            xcp[ry][i] = pack2(xc[0][i], xc[1][i]);
            ycp[ry][i] = pack2(yc[0][i], yc[1][i]);
        }
    }
    const int xl = max(wq - 1, 0);
    const int xm = wq;
    const int xr = min(wq + 1, Wn - 1);

    const int oy0 = 2 * h;
    const int ox0 = 2 * wq;

    // ---- channel loop: 9 LDS + 9 pack + 24 ffma2 + 2 STG.64 ----
    #pragma unroll
    for (int kk = 0; kk < 8; kk++) {
        const int k = kbase + kk;
        ull vp[9];
        #pragma unroll
        for (int r = 0; r < 3; r++) {
            const float vL = xs[r][k][xl];
            const float vM = xs[r][k][xm];
            const float vR = xs[r][k][xr];
            vp[r * 3 + 0] = pack2(vL, vL);
            vp[r * 3 + 1] = pack2(vM, vM);
            vp[r * 3 + 2] = pack2(vR, vR);
        }
        float* op = out + (((size_t)(cstage + k) * OH + oy0) * OW + ox0);
        #pragma unroll
        for (int ry = 0; ry < 2; ry++) {
            ull t0 = mul2(xcp[ry][0], vp[0]);
            ffma2(t0, xcp[ry][1], vp[1]);
            ffma2(t0, xcp[ry][2], vp[2]);
            ull t1 = mul2(xcp[ry][0], vp[3]);
            ffma2(t1, xcp[ry][1], vp[4]);
            ffma2(t1, xcp[ry][2], vp[5]);
            ull t2 = mul2(xcp[ry][0], vp[6]);
            ffma2(t2, xcp[ry][1], vp[7]);
            ffma2(t2, xcp[ry][2], vp[8]);
            ull a = mul2(ycp[ry][0], t0);
            ffma2(a, ycp[ry][1], t1);
            ffma2(a, ycp[ry][2], t2);
            *(ull*)(op + (size_t)ry * OW) = a;   // (lo,hi) = (rx0, rx1)
        }
    }
}

extern "C" void kernel_launch(void* const* d_in, const int* in_sizes, int n_in,
                              void* d_out, int out_size) {
    const float* x    = (const float*)d_in[0];
    const float* Woff = (const float*)d_in[1];
    const float* boff = (const float*)d_in[2];
    float* out = (float*)d_out;

    dim3 gridA(128, Bn);
    offset_kernel<<<gridA, 256>>>(x, Woff, boff);

    dim3 gridB(Hn, Bn, 8);
    gather_kernel<<<gridB, 256>>>(x, out);
}